// round 4
// baseline (speedup 1.0000x reference)
#include <cuda_runtime.h>

#define B_    8
#define C_    20
#define H_    512
#define W_    512
#define SH_   32
#define SW_   32
#define S_    1024
#define CELL_ 16
#define HW_   (H_*W_)
#define PSTR  260            // padded pixel-row stride (floats); 1040B -> 65 16B chunks
#define EPSV  1e-8f

// Scratch (device globals — no allocation allowed)
__device__ float g_seeds[B_][S_][C_];
__device__ float g_numer[B_][S_][C_];
__device__ float g_denom[B_][S_];

__constant__ int c_dy[9] = {-1,-1,-1, 0,0,0, 1,1,1};
__constant__ int c_dx[9] = {-1, 0, 1,-1,0,1,-1,0,1};

// ---------------------------------------------------------------------------
// K0: seed init = 16x16 mean pool per (b, cell, c); also zero numer/denom
// ---------------------------------------------------------------------------
__global__ void __launch_bounds__(256) k_init(const float* __restrict__ x)
{
    __shared__ __align__(16) float sX[C_][PSTR];
    const int b  = blockIdx.z, cy = blockIdx.y, cx = blockIdx.x;
    const int tid = threadIdx.x;
    const int ty = tid >> 4, tx = tid & 15;

    const float* xp = x + (size_t)b * C_ * HW_
                        + (size_t)(cy * CELL_ + ty) * W_ + (cx * CELL_ + tx);
#pragma unroll
    for (int c = 0; c < C_; c++) sX[c][tid] = xp[(size_t)c * HW_];
    __syncthreads();

    const int sidx = cy * SW_ + cx;
    if (tid < C_) {
        const float4* r = (const float4*)sX[tid];
        float a0 = 0.f, a1 = 0.f, a2 = 0.f, a3 = 0.f;
#pragma unroll
        for (int p = 0; p < 64; p++) {
            float4 v = r[p];
            a0 += v.x; a1 += v.y; a2 += v.z; a3 += v.w;
        }
        g_seeds[b][sidx][tid] = ((a0 + a1) + (a2 + a3)) * (1.f / 256.f);
        g_numer[b][sidx][tid] = 0.f;
    } else if (tid == C_) {
        g_denom[b][sidx] = 0.f;
    }
}

// ---------------------------------------------------------------------------
// Main kernel: one CTA = one (b, cell). 128 threads, each owns 2 adjacent
// pixels (P=2) — halves the broadcast seed-read wavefronts per pixel.
//
// logit[o] = 2*x.s_o - |s_o|^2   (|x|^2 cancels in softmax over o)
//
// Accumulate phase: reduction GEMM  out[o][c] = sum_p Q[o][p] * X[c][p]
// with 21 "channels" (20 + ones row) and 9 offsets. Thread tiling
// (1 o x 3 c), K split in halves; halves combined via shared; ALL barriers
// reached unconditionally by the whole CTA.
// ---------------------------------------------------------------------------
template<bool FINAL>
__global__ void __launch_bounds__(128) k_main(const float* __restrict__ x,
                                              float* __restrict__ out)
{
    __shared__ __align__(16) float sS[9][20];     // 2*seed
    __shared__ float sD0[9];                      // |seed|^2
    __shared__ int   sIdx[9];                     // clipped global seed index
    __shared__ float sPart[189];                  // K-half partials
    __shared__ __align__(16) float sXQ[30][PSTR]; // 0..19: X, 20: ones, 21..29: Q

    const int b  = blockIdx.z, cy = blockIdx.y, cx = blockIdx.x;
    const int tid = threadIdx.x;

    // Load 9x20 seed tile (pre-doubled) + neighbor indices.
    // STRIDED over 128 threads -> covers ALL 180 entries (t = tid, tid+128).
    for (int t = tid; t < 180; t += 128) {
        const int o = t / 20, c = t - o * 20;
        int iy = cy + c_dy[o]; iy = iy < 0 ? 0 : (iy > SH_ - 1 ? SH_ - 1 : iy);
        int ix = cx + c_dx[o]; ix = ix < 0 ? 0 : (ix > SW_ - 1 ? SW_ - 1 : ix);
        const int sidx = iy * SW_ + ix;
        if (c == 0) sIdx[o] = sidx;
        sS[o][c] = 2.f * g_seeds[b][sidx][c];
    }

    // Load this thread's two pixels (all 20 channels) as float2 — coalesced
    const int ty  = tid >> 3;             // 0..15
    const int tx0 = (tid & 7) * 2;        // 0,2,..,14
    const float* xp = x + (size_t)b * C_ * HW_
                        + (size_t)(cy * CELL_ + ty) * W_ + (cx * CELL_ + tx0);
    float2 xv[C_];
#pragma unroll
    for (int c = 0; c < C_; c++) xv[c] = *(const float2*)(xp + (size_t)c * HW_);

    __syncthreads();

    // |s|^2 per offset (sS holds 2s -> 0.25 * sum(t^2))
    if (tid < 9) {
        float a = 0.f;
#pragma unroll
        for (int c = 0; c < C_; c++) a += sS[tid][c] * sS[tid][c];
        sD0[tid] = 0.25f * a;
    }

    const int p0 = tid * 2;               // pixel pair base (linear in cell)
    if (!FINAL) {
        // Stage X tile + ones row for the reduction GEMM (STS.64, conflict-free)
#pragma unroll
        for (int c = 0; c < C_; c++) *(float2*)&sXQ[c][p0] = xv[c];
        *(float2*)&sXQ[20][p0] = make_float2(1.f, 1.f);
    }
    __syncthreads();

    // Logits for both pixels: 9 dot products of length 20 each; seeds via
    // uniform float4 LDS (one read serves both pixels)
    float2 q2[9];
    {
        float2 L[9];
#pragma unroll
        for (int o = 0; o < 9; o++) {
            const float4* s4 = (const float4*)sS[o];
            float a0 = 0.f, a1 = 0.f, b0 = 0.f, b1 = 0.f;
#pragma unroll
            for (int k = 0; k < 5; k++) {
                float4 t = s4[k];
                a0 = fmaf(t.x, xv[4*k+0].x, a0);
                b0 = fmaf(t.x, xv[4*k+0].y, b0);
                a1 = fmaf(t.y, xv[4*k+1].x, a1);
                b1 = fmaf(t.y, xv[4*k+1].y, b1);
                a0 = fmaf(t.z, xv[4*k+2].x, a0);
                b0 = fmaf(t.z, xv[4*k+2].y, b0);
                a1 = fmaf(t.w, xv[4*k+3].x, a1);
                b1 = fmaf(t.w, xv[4*k+3].y, b1);
            }
            const float d0 = sD0[o];
            L[o].x = a0 + a1 - d0;
            L[o].y = b0 + b1 - d0;
        }
        float mx = L[0].x, my = L[0].y;
#pragma unroll
        for (int o = 1; o < 9; o++) { mx = fmaxf(mx, L[o].x); my = fmaxf(my, L[o].y); }
        float sx = 0.f, sy = 0.f;
#pragma unroll
        for (int o = 0; o < 9; o++) {
            q2[o].x = __expf(L[o].x - mx); sx += q2[o].x;
            q2[o].y = __expf(L[o].y - my); sy += q2[o].y;
        }
        const float ix = 1.f / sx, iy = 1.f / sy;
#pragma unroll
        for (int o = 0; o < 9; o++) { q2[o].x *= ix; q2[o].y *= iy; }
    }

    if (FINAL) {
        const int yy = cy * CELL_ + ty, xx = cx * CELL_ + tx0;
        float* op = out + (size_t)b * 9 * HW_ + (size_t)yy * W_ + xx;
#pragma unroll
        for (int o = 0; o < 9; o++) *(float2*)(op + (size_t)o * HW_) = q2[o];
        return;
    }

#pragma unroll
    for (int o = 0; o < 9; o++) *(float2*)&sXQ[21 + o][p0] = q2[o];
    __syncthreads();

    // Reduction GEMM: 189 outputs, thread tiling (1 o x 3 c), K split in 2.
    // t in [0,126): kh = t/63, r = t%63, o = r%9, cg = r/9 -> c = 3*cg+j.
    const int kh = tid / 63;              // 0,1 for workers; 2 for tid>=126
    const int r  = tid - kh * 63;
    const int o  = r % 9, cg = r / 9;
    float v0 = 0.f, v1 = 0.f, v2 = 0.f;

    if (tid < 126) {
        const float4* Qr = (const float4*)sXQ[21 + o];
        const float4* X0 = (const float4*)sXQ[3 * cg + 0];
        const float4* X1 = (const float4*)sXQ[3 * cg + 1];
        const float4* X2 = (const float4*)sXQ[3 * cg + 2];
        float a00=0,a01=0,a10=0,a11=0,a20=0,a21=0;
        const int pb = kh * 32, pe = pb + 32;
#pragma unroll 8
        for (int p = pb; p < pe; p++) {
            float4 qc = Qr[p];
            float4 c0 = X0[p];
            a00 = fmaf(c0.x, qc.x, a00); a01 = fmaf(c0.y, qc.y, a01);
            a00 = fmaf(c0.z, qc.z, a00); a01 = fmaf(c0.w, qc.w, a01);
            float4 c1 = X1[p];
            a10 = fmaf(c1.x, qc.x, a10); a11 = fmaf(c1.y, qc.y, a11);
            a10 = fmaf(c1.z, qc.z, a10); a11 = fmaf(c1.w, qc.w, a11);
            float4 c2 = X2[p];
            a20 = fmaf(c2.x, qc.x, a20); a21 = fmaf(c2.y, qc.y, a21);
            a20 = fmaf(c2.z, qc.z, a20); a21 = fmaf(c2.w, qc.w, a21);
        }
        v0 = a00 + a01; v1 = a10 + a11; v2 = a20 + a21;
    }

    if (kh == 1 && tid < 126) {           // store high-half partials
        sPart[r * 3 + 0] = v0;
        sPart[r * 3 + 1] = v1;
        sPart[r * 3 + 2] = v2;
    }
    __syncthreads();                      // UNCONDITIONAL barrier

    if (tid < 63) {                       // kh == 0: combine + atomics
        v0 += sPart[r * 3 + 0];
        v1 += sPart[r * 3 + 1];
        v2 += sPart[r * 3 + 2];
        const int sidx = sIdx[o];
        const int c0 = 3 * cg;
        float* np = &g_numer[b][sidx][0];
        atomicAdd(np + c0 + 0, v0);
        atomicAdd(np + c0 + 1, v1);
        if (c0 + 2 < 20) atomicAdd(np + c0 + 2, v2);
        else             atomicAdd(&g_denom[b][sidx], v2);
    }
}

// ---------------------------------------------------------------------------
// Seed update: seeds = numer/(denom+eps); fused re-zero of numer/denom
// ---------------------------------------------------------------------------
__global__ void __launch_bounds__(32) k_update()
{
    const int bs = blockIdx.x;          // 0..8191
    const int b = bs >> 10, s = bs & 1023;
    const int l = threadIdx.x;

    float den = (l == 20) ? g_denom[b][s] : 0.f;
    den = __shfl_sync(0xffffffffu, den, 20);

    if (l < 20) {
        const float nu = g_numer[b][s][l];
        g_seeds[b][s][l] = nu / (den + EPSV);
        g_numer[b][s][l] = 0.f;
    } else if (l == 20) {
        g_denom[b][s] = 0.f;
    }
}

// ---------------------------------------------------------------------------
extern "C" void kernel_launch(void* const* d_in, const int* in_sizes, int n_in,
                              void* d_out, int out_size)
{
    const float* x = (const float*)d_in[0];
    float* out = (float*)d_out;

    dim3 grid(SW_, SH_, B_);

    k_init<<<grid, 256>>>(x);
    for (int it = 0; it < 3; it++) {
        k_main<false><<<grid, 128>>>(x, nullptr);
        k_update<<<8192, 32>>>();
    }
    k_main<true><<<grid, 128>>>(x, out);
}

// round 5
// speedup vs baseline: 1.5605x; 1.5605x over previous
#include <cuda_runtime.h>

#define B_    8
#define C_    20
#define H_    512
#define W_    512
#define SH_   32
#define SW_   32
#define S_    1024
#define CELL_ 16
#define HW_   (H_*W_)
#define PSTR  260
#define PSTR2 264            // GEMM staging stride: 66 16B-chunks (66%8==2)
#define EPSV  1e-8f

__device__ float g_seeds[B_][S_][C_];
__device__ float g_numer[B_][S_][C_];
__device__ float g_denom[B_][S_];

__constant__ int c_dy[9] = {-1,-1,-1, 0,0,0, 1,1,1};
__constant__ int c_dx[9] = {-1, 0, 1,-1,0,1,-1,0,1};

// ---------------------------------------------------------------------------
// K0: seed init = 16x16 mean pool per (b, cell, c); also zero numer/denom
// ---------------------------------------------------------------------------
__global__ void __launch_bounds__(256) k_init(const float* __restrict__ x)
{
    __shared__ __align__(16) float sX[C_][PSTR];
    const int b  = blockIdx.z, cy = blockIdx.y, cx = blockIdx.x;
    const int tid = threadIdx.x;
    const int ty = tid >> 4, tx = tid & 15;

    const float* xp = x + (size_t)b * C_ * HW_
                        + (size_t)(cy * CELL_ + ty) * W_ + (cx * CELL_ + tx);
#pragma unroll
    for (int c = 0; c < C_; c++) sX[c][tid] = xp[(size_t)c * HW_];
    __syncthreads();

    const int sidx = cy * SW_ + cx;
    if (tid < C_) {
        const float4* r = (const float4*)sX[tid];
        float a0 = 0.f, a1 = 0.f, a2 = 0.f, a3 = 0.f;
#pragma unroll
        for (int p = 0; p < 64; p++) {
            float4 v = r[p];
            a0 += v.x; a1 += v.y; a2 += v.z; a3 += v.w;
        }
        g_seeds[b][sidx][tid] = ((a0 + a1) + (a2 + a3)) * (1.f / 256.f);
        g_numer[b][sidx][tid] = 0.f;
    } else if (tid == C_) {
        g_denom[b][sidx] = 0.f;
    }
}

// ---------------------------------------------------------------------------
// Main kernel: one CTA = one (b, cell). 64 threads, each owns a quad of 4
// adjacent pixels (P=4) — seed-broadcast LDS lane-bytes scale with #threads.
//
// logit[o] = 2*x.s_o - |s_o|^2   (|x|^2 cancels in softmax over o)
//
// Accumulate iters: reduction GEMM out[o][c] = sum_p Q[o][p]*X[c][p],
// 21 channels (20 + ones) x 9 offsets. 36 GEMM threads: tile (3 o x 7 c),
// K interleaved 4-way (chunk = 4i+kq) so lane classes spread over banks.
// Partials combined in shared; one atomicAdd per output.
// ---------------------------------------------------------------------------
template<bool FINAL>
__global__ void __launch_bounds__(64) k_main(const float* __restrict__ x,
                                             float* __restrict__ out)
{
    __shared__ __align__(16) float sS[9][20];      // 2*seed
    __shared__ float sD0[9];                       // |seed|^2
    __shared__ int   sIdx[9];                      // clipped global seed index
    __shared__ float sPart[567];                   // 9 tiles x 3 kq-partials x 21
    __shared__ __align__(16) float sXQ[30][PSTR2]; // 0..19 X, 20 ones, 21..29 Q

    const int b  = blockIdx.z, cy = blockIdx.y, cx = blockIdx.x;
    const int tid = threadIdx.x;

    // Seed tile (pre-doubled) + neighbor indices, strided over 64 threads
    for (int t = tid; t < 180; t += 64) {
        const int o = t / 20, c = t - o * 20;
        int iy = cy + c_dy[o]; iy = iy < 0 ? 0 : (iy > SH_ - 1 ? SH_ - 1 : iy);
        int ix = cx + c_dx[o]; ix = ix < 0 ? 0 : (ix > SW_ - 1 ? SW_ - 1 : ix);
        const int sidx = iy * SW_ + ix;
        if (c == 0) sIdx[o] = sidx;
        sS[o][c] = 2.f * g_seeds[b][sidx][c];
    }
    __syncthreads();

    if (tid < 9) {
        float a = 0.f;
#pragma unroll
        for (int c = 0; c < C_; c++) a += sS[tid][c] * sS[tid][c];
        sD0[tid] = 0.25f * a;   // sS holds 2s
    }

    // Thread's pixel quad: ty = row in cell, tx0 = 4-aligned column
    const int ty  = tid >> 2;
    const int tx0 = (tid & 3) * 4;
    const float* xp = x + (size_t)b * C_ * HW_
                        + (size_t)(cy * CELL_ + ty) * W_ + (cx * CELL_ + tx0);
    const int p0 = tid * 4;      // linear quad base in the 256-px cell

    // Logits, streamed by channel groups of 4 (keeps regs low, MLP=4)
    float4 L[9];
#pragma unroll
    for (int o = 0; o < 9; o++) L[o] = make_float4(0.f, 0.f, 0.f, 0.f);

#pragma unroll
    for (int g = 0; g < 5; g++) {
        float4 xg[4];
#pragma unroll
        for (int j = 0; j < 4; j++)
            xg[j] = *(const float4*)(xp + (size_t)(4 * g + j) * HW_);
        if (!FINAL) {
#pragma unroll
            for (int j = 0; j < 4; j++)
                *(float4*)&sXQ[4 * g + j][p0] = xg[j];
        }
#pragma unroll
        for (int o = 0; o < 9; o++) {
            const float4 s4 = *(const float4*)&sS[o][4 * g];
            L[o].x = fmaf(s4.x, xg[0].x, L[o].x);
            L[o].y = fmaf(s4.x, xg[0].y, L[o].y);
            L[o].z = fmaf(s4.x, xg[0].z, L[o].z);
            L[o].w = fmaf(s4.x, xg[0].w, L[o].w);
            L[o].x = fmaf(s4.y, xg[1].x, L[o].x);
            L[o].y = fmaf(s4.y, xg[1].y, L[o].y);
            L[o].z = fmaf(s4.y, xg[1].z, L[o].z);
            L[o].w = fmaf(s4.y, xg[1].w, L[o].w);
            L[o].x = fmaf(s4.z, xg[2].x, L[o].x);
            L[o].y = fmaf(s4.z, xg[2].y, L[o].y);
            L[o].z = fmaf(s4.z, xg[2].z, L[o].z);
            L[o].w = fmaf(s4.z, xg[2].w, L[o].w);
            L[o].x = fmaf(s4.w, xg[3].x, L[o].x);
            L[o].y = fmaf(s4.w, xg[3].y, L[o].y);
            L[o].z = fmaf(s4.w, xg[3].z, L[o].z);
            L[o].w = fmaf(s4.w, xg[3].w, L[o].w);
        }
    }
    if (!FINAL) *(float4*)&sXQ[20][p0] = make_float4(1.f, 1.f, 1.f, 1.f);

    __syncthreads();   // sD0 visible; X staging complete

    // Subtract |s|^2, softmax over o (componentwise over the 4 pixels)
#pragma unroll
    for (int o = 0; o < 9; o++) {
        const float d0 = sD0[o];
        L[o].x -= d0; L[o].y -= d0; L[o].z -= d0; L[o].w -= d0;
    }
    float4 m = L[0];
#pragma unroll
    for (int o = 1; o < 9; o++) {
        m.x = fmaxf(m.x, L[o].x); m.y = fmaxf(m.y, L[o].y);
        m.z = fmaxf(m.z, L[o].z); m.w = fmaxf(m.w, L[o].w);
    }
    float4 sum = make_float4(0.f, 0.f, 0.f, 0.f);
#pragma unroll
    for (int o = 0; o < 9; o++) {
        L[o].x = __expf(L[o].x - m.x); sum.x += L[o].x;
        L[o].y = __expf(L[o].y - m.y); sum.y += L[o].y;
        L[o].z = __expf(L[o].z - m.z); sum.z += L[o].z;
        L[o].w = __expf(L[o].w - m.w); sum.w += L[o].w;
    }
    const float4 inv = make_float4(1.f / sum.x, 1.f / sum.y, 1.f / sum.z, 1.f / sum.w);
#pragma unroll
    for (int o = 0; o < 9; o++) {
        L[o].x *= inv.x; L[o].y *= inv.y; L[o].z *= inv.z; L[o].w *= inv.w;
    }

    if (FINAL) {
        const int yy = cy * CELL_ + ty, xx = cx * CELL_ + tx0;
        float* op = out + (size_t)b * 9 * HW_ + (size_t)yy * W_ + xx;
#pragma unroll
        for (int o = 0; o < 9; o++) *(float4*)(op + (size_t)o * HW_) = L[o];
        return;
    }

#pragma unroll
    for (int o = 0; o < 9; o++) *(float4*)&sXQ[21 + o][p0] = L[o];
    __syncthreads();

    // Reduction GEMM: 36 threads = 9 output tiles (3o x 7c) x 4 K-slices.
    // tid = t2*4 + kq ; og = t2%3, cgr = t2/3. Chunk = 4*i + kq (i<16).
    const int t2 = tid >> 2, kq = tid & 3;
    float acc[3][7];
#pragma unroll
    for (int jo = 0; jo < 3; jo++)
#pragma unroll
        for (int jc = 0; jc < 7; jc++) acc[jo][jc] = 0.f;

    if (tid < 36) {
        const int og = t2 % 3, cgr = t2 / 3;
#pragma unroll 4
        for (int i = 0; i < 16; i++) {
            const int ck = 4 * i + kq;
            float4 qv[3];
#pragma unroll
            for (int jo = 0; jo < 3; jo++)
                qv[jo] = ((const float4*)&sXQ[21 + 3 * og + jo][0])[ck];
#pragma unroll
            for (int jc = 0; jc < 7; jc++) {
                const float4 xc = ((const float4*)&sXQ[7 * cgr + jc][0])[ck];
#pragma unroll
                for (int jo = 0; jo < 3; jo++) {
                    acc[jo][jc] = fmaf(xc.x, qv[jo].x, acc[jo][jc]);
                    acc[jo][jc] = fmaf(xc.y, qv[jo].y, acc[jo][jc]);
                    acc[jo][jc] = fmaf(xc.z, qv[jo].z, acc[jo][jc]);
                    acc[jo][jc] = fmaf(xc.w, qv[jo].w, acc[jo][jc]);
                }
            }
        }
    }

    if (tid < 36 && kq > 0) {
        float* dst = &sPart[((t2 * 3) + (kq - 1)) * 21];
#pragma unroll
        for (int jo = 0; jo < 3; jo++)
#pragma unroll
            for (int jc = 0; jc < 7; jc++) dst[jo * 7 + jc] = acc[jo][jc];
    }
    __syncthreads();                      // unconditional

    if (tid < 36 && kq == 0) {
        const int og = t2 % 3, cgr = t2 / 3;
#pragma unroll
        for (int p = 0; p < 3; p++) {
            const float* src = &sPart[(t2 * 3 + p) * 21];
#pragma unroll
            for (int jo = 0; jo < 3; jo++)
#pragma unroll
                for (int jc = 0; jc < 7; jc++) acc[jo][jc] += src[jo * 7 + jc];
        }
#pragma unroll
        for (int jo = 0; jo < 3; jo++) {
            const int o = 3 * og + jo;
            const int sidx = sIdx[o];
#pragma unroll
            for (int jc = 0; jc < 7; jc++) {
                const int c = 7 * cgr + jc;
                if (c < 20) atomicAdd(&g_numer[b][sidx][c], acc[jo][jc]);
                else        atomicAdd(&g_denom[b][sidx],    acc[jo][jc]);
            }
        }
    }
}

// ---------------------------------------------------------------------------
// Seed update: seeds = numer/(denom+eps); fused re-zero of numer/denom
// ---------------------------------------------------------------------------
__global__ void __launch_bounds__(32) k_update()
{
    const int bs = blockIdx.x;          // 0..8191
    const int b = bs >> 10, s = bs & 1023;
    const int l = threadIdx.x;

    float den = (l == 20) ? g_denom[b][s] : 0.f;
    den = __shfl_sync(0xffffffffu, den, 20);

    if (l < 20) {
        const float nu = g_numer[b][s][l];
        g_seeds[b][s][l] = nu / (den + EPSV);
        g_numer[b][s][l] = 0.f;
    } else if (l == 20) {
        g_denom[b][s] = 0.f;
    }
}

// ---------------------------------------------------------------------------
extern "C" void kernel_launch(void* const* d_in, const int* in_sizes, int n_in,
                              void* d_out, int out_size)
{
    const float* x = (const float*)d_in[0];
    float* out = (float*)d_out;

    dim3 grid(SW_, SH_, B_);

    k_init<<<grid, 256>>>(x);
    for (int it = 0; it < 3; it++) {
        k_main<false><<<grid, 64>>>(x, nullptr);
        k_update<<<8192, 32>>>();
    }
    k_main<true><<<grid, 64>>>(x, out);
}

// round 7
// speedup vs baseline: 1.8609x; 1.1925x over previous
#include <cuda_runtime.h>

#define B_    8
#define C_    20
#define H_    512
#define W_    512
#define SH_   32
#define SW_   32
#define S_    1024
#define CELL_ 16
#define HW_   (H_*W_)
#define PSTR  260
#define PSTRQ 264            // Q staging stride (floats): 66 16B-chunks
#define EPSV  1e-8f

__device__ float g_seeds[B_][S_][C_];
__device__ float g_numer[B_][S_][C_];
__device__ float g_denom[B_][S_];

__constant__ int c_dy[9] = {-1,-1,-1, 0,0,0, 1,1,1};
__constant__ int c_dx[9] = {-1, 0, 1,-1,0,1,-1,0,1};

// ---------------------------------------------------------------------------
// K0: seed init = 16x16 mean pool per (b, cell, c); also zero numer/denom
// ---------------------------------------------------------------------------
__global__ void __launch_bounds__(256) k_init(const float* __restrict__ x)
{
    __shared__ __align__(16) float sX[C_][PSTR];
    const int b  = blockIdx.z, cy = blockIdx.y, cx = blockIdx.x;
    const int tid = threadIdx.x;
    const int ty = tid >> 4, tx = tid & 15;

    const float* xp = x + (size_t)b * C_ * HW_
                        + (size_t)(cy * CELL_ + ty) * W_ + (cx * CELL_ + tx);
#pragma unroll
    for (int c = 0; c < C_; c++) sX[c][tid] = xp[(size_t)c * HW_];
    __syncthreads();

    const int sidx = cy * SW_ + cx;
    if (tid < C_) {
        const float4* r = (const float4*)sX[tid];
        float a0 = 0.f, a1 = 0.f, a2 = 0.f, a3 = 0.f;
#pragma unroll
        for (int p = 0; p < 64; p++) {
            float4 v = r[p];
            a0 += v.x; a1 += v.y; a2 += v.z; a3 += v.w;
        }
        g_seeds[b][sidx][tid] = ((a0 + a1) + (a2 + a3)) * (1.f / 256.f);
        g_numer[b][sidx][tid] = 0.f;
    } else if (tid == C_) {
        g_denom[b][sidx] = 0.f;
    }
}

// ---------------------------------------------------------------------------
// Main kernel: one CTA = one (b, cell). 64 threads, thread = 4 adjacent px.
// logit[o] = 2*x.s_o - |s_o|^2  (|x|^2 cancels in softmax over o)
//
// Accumulate iters:
//  - denominators: Sigma_p Q[o][p] via register quad-sums + shfl butterfly
//  - numerators:   GEMM out[o][c] = Sigma_p Q[o][p]*X[c][p];
//                  Q staged in smem; X RE-READ from global (L1/L2-hot) —
//                  saves 21KB smem/CTA -> occupancy 6 -> 10 CTAs/SM.
//  - 48 GEMM threads: 12 tiles (3 o x 5 c) x 4 K-slices; partials combined
//    in smem; one atomicAdd per output.
// ---------------------------------------------------------------------------
template<bool FINAL>
__global__ void __launch_bounds__(64, 10) k_main(const float* __restrict__ x,
                                                 float* __restrict__ out)
{
    __shared__ __align__(16) float sS[9][20];      // 2*seed
    __shared__ float sD0[9];                       // |seed|^2
    __shared__ int   sIdx[9];                      // clipped global seed index
    __shared__ float sDen[9];                      // warp-1 denom partials
    __shared__ float sPart[540];                   // 12 tiles x 3 kq x 15
    __shared__ __align__(16) float sQ[9][PSTRQ];   // staged Q

    const int b  = blockIdx.z, cy = blockIdx.y, cx = blockIdx.x;
    const int tid = threadIdx.x;

    // Seed tile (pre-doubled) + neighbor indices, strided over 64 threads
    for (int t = tid; t < 180; t += 64) {
        const int o = t / 20, c = t - o * 20;
        int iy = cy + c_dy[o]; iy = iy < 0 ? 0 : (iy > SH_ - 1 ? SH_ - 1 : iy);
        int ix = cx + c_dx[o]; ix = ix < 0 ? 0 : (ix > SW_ - 1 ? SW_ - 1 : ix);
        const int sidx = iy * SW_ + ix;
        if (c == 0) sIdx[o] = sidx;
        sS[o][c] = 2.f * g_seeds[b][sidx][c];
    }
    __syncthreads();

    if (tid < 9) {
        float a = 0.f;
#pragma unroll
        for (int c = 0; c < C_; c++) a += sS[tid][c] * sS[tid][c];
        sD0[tid] = 0.25f * a;   // sS holds 2s
    }

    // Thread's pixel quad
    const int ty  = tid >> 2;
    const int tx0 = (tid & 3) * 4;
    const float* xp = x + (size_t)b * C_ * HW_
                        + (size_t)(cy * CELL_ + ty) * W_ + (cx * CELL_ + tx0);
    const int p0 = tid * 4;

    // Logits streamed by channel groups of 4
    float4 L[9];
#pragma unroll
    for (int o = 0; o < 9; o++) L[o] = make_float4(0.f, 0.f, 0.f, 0.f);

#pragma unroll
    for (int g = 0; g < 5; g++) {
        float4 xg[4];
#pragma unroll
        for (int j = 0; j < 4; j++)
            xg[j] = *(const float4*)(xp + (size_t)(4 * g + j) * HW_);
#pragma unroll
        for (int o = 0; o < 9; o++) {
            const float4 s4 = *(const float4*)&sS[o][4 * g];
            L[o].x = fmaf(s4.x, xg[0].x, L[o].x);
            L[o].y = fmaf(s4.x, xg[0].y, L[o].y);
            L[o].z = fmaf(s4.x, xg[0].z, L[o].z);
            L[o].w = fmaf(s4.x, xg[0].w, L[o].w);
            L[o].x = fmaf(s4.y, xg[1].x, L[o].x);
            L[o].y = fmaf(s4.y, xg[1].y, L[o].y);
            L[o].z = fmaf(s4.y, xg[1].z, L[o].z);
            L[o].w = fmaf(s4.y, xg[1].w, L[o].w);
            L[o].x = fmaf(s4.z, xg[2].x, L[o].x);
            L[o].y = fmaf(s4.z, xg[2].y, L[o].y);
            L[o].z = fmaf(s4.z, xg[2].z, L[o].z);
            L[o].w = fmaf(s4.z, xg[2].w, L[o].w);
            L[o].x = fmaf(s4.w, xg[3].x, L[o].x);
            L[o].y = fmaf(s4.w, xg[3].y, L[o].y);
            L[o].z = fmaf(s4.w, xg[3].z, L[o].z);
            L[o].w = fmaf(s4.w, xg[3].w, L[o].w);
        }
    }
    __syncthreads();   // sD0 ready

    // Subtract |s|^2, softmax over o (componentwise over the 4 pixels)
#pragma unroll
    for (int o = 0; o < 9; o++) {
        const float d0 = sD0[o];
        L[o].x -= d0; L[o].y -= d0; L[o].z -= d0; L[o].w -= d0;
    }
    float4 m = L[0];
#pragma unroll
    for (int o = 1; o < 9; o++) {
        m.x = fmaxf(m.x, L[o].x); m.y = fmaxf(m.y, L[o].y);
        m.z = fmaxf(m.z, L[o].z); m.w = fmaxf(m.w, L[o].w);
    }
    float4 sum = make_float4(0.f, 0.f, 0.f, 0.f);
#pragma unroll
    for (int o = 0; o < 9; o++) {
        L[o].x = __expf(L[o].x - m.x); sum.x += L[o].x;
        L[o].y = __expf(L[o].y - m.y); sum.y += L[o].y;
        L[o].z = __expf(L[o].z - m.z); sum.z += L[o].z;
        L[o].w = __expf(L[o].w - m.w); sum.w += L[o].w;
    }
    const float4 inv = make_float4(1.f / sum.x, 1.f / sum.y,
                                   1.f / sum.z, 1.f / sum.w);
#pragma unroll
    for (int o = 0; o < 9; o++) {
        L[o].x *= inv.x; L[o].y *= inv.y; L[o].z *= inv.z; L[o].w *= inv.w;
    }

    if (FINAL) {
        const int yy = cy * CELL_ + ty, xx = cx * CELL_ + tx0;
        float* op = out + (size_t)b * 9 * HW_ + (size_t)yy * W_ + xx;
#pragma unroll
        for (int o = 0; o < 9; o++) *(float4*)(op + (size_t)o * HW_) = L[o];
        return;
    }

    // Stage Q + per-thread denom quad sums
    float qs[9];
#pragma unroll
    for (int o = 0; o < 9; o++) {
        *(float4*)&sQ[o][p0] = L[o];
        qs[o] = (L[o].x + L[o].y) + (L[o].z + L[o].w);
    }
    // warp butterfly: all lanes end with warp total
#pragma unroll
    for (int o = 0; o < 9; o++) {
#pragma unroll
        for (int d = 16; d >= 1; d >>= 1)
            qs[o] += __shfl_xor_sync(0xffffffffu, qs[o], d);
    }
    if (tid == 32) {
#pragma unroll
        for (int o = 0; o < 9; o++) sDen[o] = qs[o];
    }
    __syncthreads();   // Q staged + sDen ready

    if (tid == 0) {
#pragma unroll
        for (int o = 0; o < 9; o++)
            atomicAdd(&g_denom[b][sIdx[o]], qs[o] + sDen[o]);
    }

    // Reduction GEMM: 48 threads = 12 tiles (3o x 5c) x 4 K-slices (kq).
    // Chunk ck = 4*i + kq maps to pixel row py=i, col-quad kq.
    const int t2 = tid >> 2, kq = tid & 3;
    float acc[3][5];
#pragma unroll
    for (int jo = 0; jo < 3; jo++)
#pragma unroll
        for (int jc = 0; jc < 5; jc++) acc[jo][jc] = 0.f;

    if (tid < 48) {
        const int og = t2 % 3, cgr = t2 / 3;     // og 0..2, cgr 0..3
        const float4* xb = (const float4*)(x + (size_t)b * C_ * HW_
                                             + (size_t)(cy * CELL_) * W_
                                             + cx * CELL_);
        const float4* px[5];
#pragma unroll
        for (int jc = 0; jc < 5; jc++)
            px[jc] = xb + (size_t)(5 * cgr + jc) * (HW_ / 4) + kq;
#pragma unroll 4
        for (int i = 0; i < 16; i++) {
            const int ck = 4 * i + kq;
            float4 qv[3];
#pragma unroll
            for (int jo = 0; jo < 3; jo++)
                qv[jo] = ((const float4*)&sQ[3 * og + jo][0])[ck];
#pragma unroll
            for (int jc = 0; jc < 5; jc++) {
                const float4 xc = px[jc][i * (W_ / 4)];
#pragma unroll
                for (int jo = 0; jo < 3; jo++) {
                    acc[jo][jc] = fmaf(xc.x, qv[jo].x, acc[jo][jc]);
                    acc[jo][jc] = fmaf(xc.y, qv[jo].y, acc[jo][jc]);
                    acc[jo][jc] = fmaf(xc.z, qv[jo].z, acc[jo][jc]);
                    acc[jo][jc] = fmaf(xc.w, qv[jo].w, acc[jo][jc]);
                }
            }
        }
    }

    if (tid < 48 && kq > 0) {
        float* dst = &sPart[(t2 * 3 + (kq - 1)) * 15];
#pragma unroll
        for (int jo = 0; jo < 3; jo++)
#pragma unroll
            for (int jc = 0; jc < 5; jc++) dst[jo * 5 + jc] = acc[jo][jc];
    }
    __syncthreads();   // unconditional

    if (tid < 48 && kq == 0) {
        const int og = t2 % 3, cgr = t2 / 3;
#pragma unroll
        for (int p = 0; p < 3; p++) {
            const float* src = &sPart[(t2 * 3 + p) * 15];
#pragma unroll
            for (int jo = 0; jo < 3; jo++)
#pragma unroll
                for (int jc = 0; jc < 5; jc++) acc[jo][jc] += src[jo * 5 + jc];
        }
#pragma unroll
        for (int jo = 0; jo < 3; jo++) {
            const int sidx = sIdx[3 * og + jo];
#pragma unroll
            for (int jc = 0; jc < 5; jc++)
                atomicAdd(&g_numer[b][sidx][5 * cgr + jc], acc[jo][jc]);
        }
    }
}

// ---------------------------------------------------------------------------
// Seed update: seeds = numer/(denom+eps); fused re-zero of numer/denom
// ---------------------------------------------------------------------------
__global__ void __launch_bounds__(32) k_update()
{
    const int bs = blockIdx.x;          // 0..8191
    const int b = bs >> 10, s = bs & 1023;
    const int l = threadIdx.x;

    float den = (l == 20) ? g_denom[b][s] : 0.f;
    den = __shfl_sync(0xffffffffu, den, 20);

    if (l < 20) {
        const float nu = g_numer[b][s][l];
        g_seeds[b][s][l] = nu / (den + EPSV);
        g_numer[b][s][l] = 0.f;
    } else if (l == 20) {
        g_denom[b][s] = 0.f;
    }
}

// ---------------------------------------------------------------------------
extern "C" void kernel_launch(void* const* d_in, const int* in_sizes, int n_in,
                              void* d_out, int out_size)
{
    const float* x = (const float*)d_in[0];
    float* out = (float*)d_out;

    dim3 grid(SW_, SH_, B_);

    k_init<<<grid, 256>>>(x);
    for (int it = 0; it < 3; it++) {
        k_main<false><<<grid, 64>>>(x, nullptr);
        k_update<<<8192, 32>>>();
    }
    k_main<true><<<grid, 64>>>(x, out);
}

// round 9
// speedup vs baseline: 1.8724x; 1.0062x over previous
#include <cuda_runtime.h>

#define B_    8
#define C_    20
#define H_    512
#define W_    512
#define SH_   32
#define SW_   32
#define S_    1024
#define CELL_ 16
#define HW_   (H_*W_)
#define PSTR  260
#define PSTRQ 264            // Q staging stride (floats): 66 16B-chunks
#define EPSV  1e-8f

__device__ float g_seeds[B_][S_][C_];
__device__ float g_numer[B_][S_][C_];
__device__ float g_denom[B_][S_];

__constant__ int c_dy[9] = {-1,-1,-1, 0,0,0, 1,1,1};
__constant__ int c_dx[9] = {-1, 0, 1,-1,0,1,-1,0,1};

// ---------------------------------------------------------------------------
// K0: seed init = 16x16 mean pool per (b, cell, c); also zero numer/denom
// ---------------------------------------------------------------------------
__global__ void __launch_bounds__(256) k_init(const float* __restrict__ x)
{
    __shared__ __align__(16) float sX[C_][PSTR];
    const int b  = blockIdx.z, cy = blockIdx.y, cx = blockIdx.x;
    const int tid = threadIdx.x;
    const int ty = tid >> 4, tx = tid & 15;

    const float* xp = x + (size_t)b * C_ * HW_
                        + (size_t)(cy * CELL_ + ty) * W_ + (cx * CELL_ + tx);
#pragma unroll
    for (int c = 0; c < C_; c++) sX[c][tid] = xp[(size_t)c * HW_];
    __syncthreads();

    const int sidx = cy * SW_ + cx;
    if (tid < C_) {
        const float4* r = (const float4*)sX[tid];
        float a0 = 0.f, a1 = 0.f, a2 = 0.f, a3 = 0.f;
#pragma unroll
        for (int p = 0; p < 64; p++) {
            float4 v = r[p];
            a0 += v.x; a1 += v.y; a2 += v.z; a3 += v.w;
        }
        g_seeds[b][sidx][tid] = ((a0 + a1) + (a2 + a3)) * (1.f / 256.f);
        g_numer[b][sidx][tid] = 0.f;
    } else if (tid == C_) {
        g_denom[b][sidx] = 0.f;
    }
}

// ---------------------------------------------------------------------------
// Main kernel: one CTA = one (b, cell). 64 threads, thread = 4 adjacent px.
// logit[o] = 2*x.s_o - |s_o|^2  (|x|^2 cancels in softmax over o)
//
// Accumulate iters:
//  - denominators: Sigma_p Q[o][p] via register quad-sums + shfl butterfly
//  - numerators:   GEMM out[o][c] = Sigma_p Q[o][p]*X[c][p];
//                  Q staged in smem; X re-read from global (L1-hot).
//  - 48 GEMM threads: 12 tiles (3 o x 5 c) x 4 K-slices; partials combined
//    in smem; one atomicAdd per output.
// 12 CTAs/SM target (regs <= 85) — occupancy was the binding limit at 10.
// ---------------------------------------------------------------------------
template<bool FINAL>
__global__ void __launch_bounds__(64, 12) k_main(const float* __restrict__ x,
                                                 float* __restrict__ out)
{
    __shared__ __align__(16) float sS[9][20];      // 2*seed
    __shared__ float sD0[9];                       // |seed|^2
    __shared__ int   sIdx[9];                      // clipped global seed index
    __shared__ float sDen[9];                      // warp-1 denom partials
    __shared__ float sPart[540];                   // 12 tiles x 3 kq x 15
    __shared__ __align__(16) float sQ[9][PSTRQ];   // staged Q

    const int b  = blockIdx.z, cy = blockIdx.y, cx = blockIdx.x;
    const int tid = threadIdx.x;

    // Seed tile (pre-doubled) + neighbor indices, strided over 64 threads
    for (int t = tid; t < 180; t += 64) {
        const int o = t / 20, c = t - o * 20;
        int iy = cy + c_dy[o]; iy = iy < 0 ? 0 : (iy > SH_ - 1 ? SH_ - 1 : iy);
        int ix = cx + c_dx[o]; ix = ix < 0 ? 0 : (ix > SW_ - 1 ? SW_ - 1 : ix);
        const int sidx = iy * SW_ + ix;
        if (c == 0) sIdx[o] = sidx;
        sS[o][c] = 2.f * g_seeds[b][sidx][c];
    }
    __syncthreads();

    if (tid < 9) {
        float a = 0.f;
#pragma unroll
        for (int c = 0; c < C_; c++) a += sS[tid][c] * sS[tid][c];
        sD0[tid] = 0.25f * a;   // sS holds 2s
    }

    // Thread's pixel quad
    const int ty  = tid >> 2;
    const int tx0 = (tid & 3) * 4;
    const float* xp = x + (size_t)b * C_ * HW_
                        + (size_t)(cy * CELL_ + ty) * W_ + (cx * CELL_ + tx0);
    const int p0 = tid * 4;

    // Logits streamed by channel groups of 4
    float4 L[9];
#pragma unroll
    for (int o = 0; o < 9; o++) L[o] = make_float4(0.f, 0.f, 0.f, 0.f);

#pragma unroll
    for (int g = 0; g < 5; g++) {
        float4 xg[4];
#pragma unroll
        for (int j = 0; j < 4; j++)
            xg[j] = *(const float4*)(xp + (size_t)(4 * g + j) * HW_);
#pragma unroll
        for (int o = 0; o < 9; o++) {
            const float4 s4 = *(const float4*)&sS[o][4 * g];
            L[o].x = fmaf(s4.x, xg[0].x, L[o].x);
            L[o].y = fmaf(s4.x, xg[0].y, L[o].y);
            L[o].z = fmaf(s4.x, xg[0].z, L[o].z);
            L[o].w = fmaf(s4.x, xg[0].w, L[o].w);
            L[o].x = fmaf(s4.y, xg[1].x, L[o].x);
            L[o].y = fmaf(s4.y, xg[1].y, L[o].y);
            L[o].z = fmaf(s4.y, xg[1].z, L[o].z);
            L[o].w = fmaf(s4.y, xg[1].w, L[o].w);
            L[o].x = fmaf(s4.z, xg[2].x, L[o].x);
            L[o].y = fmaf(s4.z, xg[2].y, L[o].y);
            L[o].z = fmaf(s4.z, xg[2].z, L[o].z);
            L[o].w = fmaf(s4.z, xg[2].w, L[o].w);
            L[o].x = fmaf(s4.w, xg[3].x, L[o].x);
            L[o].y = fmaf(s4.w, xg[3].y, L[o].y);
            L[o].z = fmaf(s4.w, xg[3].z, L[o].z);
            L[o].w = fmaf(s4.w, xg[3].w, L[o].w);
        }
    }
    __syncthreads();   // sD0 ready

    // Subtract |s|^2, softmax over o (componentwise over the 4 pixels)
#pragma unroll
    for (int o = 0; o < 9; o++) {
        const float d0 = sD0[o];
        L[o].x -= d0; L[o].y -= d0; L[o].z -= d0; L[o].w -= d0;
    }
    float4 m = L[0];
#pragma unroll
    for (int o = 1; o < 9; o++) {
        m.x = fmaxf(m.x, L[o].x); m.y = fmaxf(m.y, L[o].y);
        m.z = fmaxf(m.z, L[o].z); m.w = fmaxf(m.w, L[o].w);
    }
    float4 sum = make_float4(0.f, 0.f, 0.f, 0.f);
#pragma unroll
    for (int o = 0; o < 9; o++) {
        L[o].x = __expf(L[o].x - m.x); sum.x += L[o].x;
        L[o].y = __expf(L[o].y - m.y); sum.y += L[o].y;
        L[o].z = __expf(L[o].z - m.z); sum.z += L[o].z;
        L[o].w = __expf(L[o].w - m.w); sum.w += L[o].w;
    }
    const float4 inv = make_float4(1.f / sum.x, 1.f / sum.y,
                                   1.f / sum.z, 1.f / sum.w);
#pragma unroll
    for (int o = 0; o < 9; o++) {
        L[o].x *= inv.x; L[o].y *= inv.y; L[o].z *= inv.z; L[o].w *= inv.w;
    }

    if (FINAL) {
        const int yy = cy * CELL_ + ty, xx = cx * CELL_ + tx0;
        float* op = out + (size_t)b * 9 * HW_ + (size_t)yy * W_ + xx;
#pragma unroll
        for (int o = 0; o < 9; o++) *(float4*)(op + (size_t)o * HW_) = L[o];
        return;
    }

    // Stage Q + per-thread denom quad sums
    float qs[9];
#pragma unroll
    for (int o = 0; o < 9; o++) {
        *(float4*)&sQ[o][p0] = L[o];
        qs[o] = (L[o].x + L[o].y) + (L[o].z + L[o].w);
    }
    // warp butterfly: all lanes end with warp total
#pragma unroll
    for (int o = 0; o < 9; o++) {
#pragma unroll
        for (int d = 16; d >= 1; d >>= 1)
            qs[o] += __shfl_xor_sync(0xffffffffu, qs[o], d);
    }
    if (tid == 32) {
#pragma unroll
        for (int o = 0; o < 9; o++) sDen[o] = qs[o];
    }
    __syncthreads();   // Q staged + sDen ready

    if (tid == 0) {
#pragma unroll
        for (int o = 0; o < 9; o++)
            atomicAdd(&g_denom[b][sIdx[o]], qs[o] + sDen[o]);
    }

    // Reduction GEMM: 48 threads = 12 tiles (3o x 5c) x 4 K-slices (kq).
    // Chunk ck = 4*i + kq maps to pixel row py=i, col-quad kq.
    const int t2 = tid >> 2, kq = tid & 3;
    float acc[3][5];
#pragma unroll
    for (int jo = 0; jo < 3; jo++)
#pragma unroll
        for (int jc = 0; jc < 5; jc++) acc[jo][jc] = 0.f;

    if (tid < 48) {
        const int og = t2 % 3, cgr = t2 / 3;     // og 0..2, cgr 0..3
        const float4* xb = (const float4*)(x + (size_t)b * C_ * HW_
                                             + (size_t)(cy * CELL_) * W_
                                             + cx * CELL_);
        const float4* px[5];
#pragma unroll
        for (int jc = 0; jc < 5; jc++)
            px[jc] = xb + (size_t)(5 * cgr + jc) * (HW_ / 4) + kq;
#pragma unroll 4
        for (int i = 0; i < 16; i++) {
            const int ck = 4 * i + kq;
            float4 qv[3];
#pragma unroll
            for (int jo = 0; jo < 3; jo++)
                qv[jo] = ((const float4*)&sQ[3 * og + jo][0])[ck];
#pragma unroll
            for (int jc = 0; jc < 5; jc++) {
                const float4 xc = px[jc][i * (W_ / 4)];
#pragma unroll
                for (int jo = 0; jo < 3; jo++) {
                    acc[jo][jc] = fmaf(xc.x, qv[jo].x, acc[jo][jc]);
                    acc[jo][jc] = fmaf(xc.y, qv[jo].y, acc[jo][jc]);
                    acc[jo][jc] = fmaf(xc.z, qv[jo].z, acc[jo][jc]);
                    acc[jo][jc] = fmaf(xc.w, qv[jo].w, acc[jo][jc]);
                }
            }
        }
    }

    if (tid < 48 && kq > 0) {
        float* dst = &sPart[(t2 * 3 + (kq - 1)) * 15];
#pragma unroll
        for (int jo = 0; jo < 3; jo++)
#pragma unroll
            for (int jc = 0; jc < 5; jc++) dst[jo * 5 + jc] = acc[jo][jc];
    }
    __syncthreads();   // unconditional

    if (tid < 48 && kq == 0) {
        const int og = t2 % 3, cgr = t2 / 3;
#pragma unroll
        for (int p = 0; p < 3; p++) {
            const float* src = &sPart[(t2 * 3 + p) * 15];
#pragma unroll
            for (int jo = 0; jo < 3; jo++)
#pragma unroll
                for (int jc = 0; jc < 5; jc++) acc[jo][jc] += src[jo * 5 + jc];
        }
#pragma unroll
        for (int jo = 0; jo < 3; jo++) {
            const int sidx = sIdx[3 * og + jo];
#pragma unroll
            for (int jc = 0; jc < 5; jc++)
                atomicAdd(&g_numer[b][sidx][5 * cgr + jc], acc[jo][jc]);
        }
    }
}

// ---------------------------------------------------------------------------
// Seed update: seeds = numer/(denom+eps); fused re-zero of numer/denom.
// 256 threads = 8 seed groups of 32 lanes (fewer, fatter blocks).
// ---------------------------------------------------------------------------
__global__ void __launch_bounds__(256) k_update()
{
    const int grp = blockIdx.x * 8 + (threadIdx.x >> 5);  // 0..8191
    const int b = grp >> 10, s = grp & 1023;
    const int l = threadIdx.x & 31;

    float den = (l == 20) ? g_denom[b][s] : 0.f;
    den = __shfl_sync(0xffffffffu, den, 20);

    if (l < 20) {
        const float nu = g_numer[b][s][l];
        g_seeds[b][s][l] = nu / (den + EPSV);
        g_numer[b][s][l] = 0.f;
    } else if (l == 20) {
        g_denom[b][s] = 0.f;
    }
}

// ---------------------------------------------------------------------------
extern "C" void kernel_launch(void* const* d_in, const int* in_sizes, int n_in,
                              void* d_out, int out_size)
{
    const float* x = (const float*)d_in[0];
    float* out = (float*)d_out;

    dim3 grid(SW_, SH_, B_);

    k_init<<<grid, 256>>>(x);
    for (int it = 0; it < 3; it++) {
        k_main<false><<<grid, 64>>>(x, nullptr);
        k_update<<<1024, 256>>>();
    }
    k_main<true><<<grid, 64>>>(x, out);
}

// round 12
// speedup vs baseline: 1.9823x; 1.0587x over previous
#include <cuda_runtime.h>

#define B_    8
#define C_    20
#define H_    512
#define W_    512
#define SH_   32
#define SW_   32
#define S_    1024
#define CELL_ 16
#define HW_   (H_*W_)
#define PSTR  260
#define PSTRQ 264            // Q staging stride (floats): 66 16B-chunks
#define EPSV  1e-8f

__device__ float g_seeds[B_][S_][C_];          // iteration-0 seeds (means)
__device__ float g_numerB[3][B_][S_][C_];      // per-iteration accumulators
__device__ float g_denomB[3][B_][S_];

__constant__ int c_dy[9] = {-1,-1,-1, 0,0,0, 1,1,1};
__constant__ int c_dx[9] = {-1, 0, 1,-1,0,1,-1,0,1};

// ---------------------------------------------------------------------------
// K0: seed init = 16x16 mean pool per (b, cell, c); zero ALL 3 accumulator
// buffers (k_update is gone — division is fused into k_main's seed loader).
// ---------------------------------------------------------------------------
__global__ void __launch_bounds__(256) k_init(const float* __restrict__ x)
{
    __shared__ __align__(16) float sX[C_][PSTR];
    const int b  = blockIdx.z, cy = blockIdx.y, cx = blockIdx.x;
    const int tid = threadIdx.x;
    const int ty = tid >> 4, tx = tid & 15;
    const int sidx = cy * SW_ + cx;

    // Zero the 3 accumulator buffers for this (b, sidx)
    if (tid < 63) {
        const int buf = tid / 21, c = tid % 21;
        if (c < 20) g_numerB[buf][b][sidx][c] = 0.f;
        else        g_denomB[buf][b][sidx]    = 0.f;
    }

    const float* xp = x + (size_t)b * C_ * HW_
                        + (size_t)(cy * CELL_ + ty) * W_ + (cx * CELL_ + tx);
#pragma unroll
    for (int c = 0; c < C_; c++) sX[c][tid] = xp[(size_t)c * HW_];
    __syncthreads();

    if (tid < C_) {
        const float4* r = (const float4*)sX[tid];
        float a0 = 0.f, a1 = 0.f, a2 = 0.f, a3 = 0.f;
#pragma unroll
        for (int p = 0; p < 64; p++) {
            float4 v = r[p];
            a0 += v.x; a1 += v.y; a2 += v.z; a3 += v.w;
        }
        g_seeds[b][sidx][tid] = ((a0 + a1) + (a2 + a3)) * (1.f / 256.f);
    }
}

// ---------------------------------------------------------------------------
// Main kernel: one CTA = one (b, cell). 64 threads, thread = 4 adjacent px.
// logit[o] = 2*x.s_o - |s_o|^2  (|x|^2 cancels in softmax over o)
//
// SRC = 0: seeds from g_seeds; SRC>0: seeds = numerB[SRC-1]/denomB[SRC-1]
// (division fused into the seed loader). !FINAL accumulates into buf SRC.
// Prefetching: g=0 x-loads issued before the seed barrier; GEMM i=0 X loads
// issued before the Q-staging barrier (peeled iterations).
// ---------------------------------------------------------------------------
template<int SRC, bool FINAL>
__global__ void __launch_bounds__(64, 12) k_main(const float* __restrict__ x,
                                                 float* __restrict__ out)
{
    __shared__ __align__(16) float sS[9][20];      // 2*seed
    __shared__ float sD0[9];                       // |seed|^2
    __shared__ int   sIdx[9];                      // clipped global seed index
    __shared__ float sDen[9];                      // warp-1 denom partials
    __shared__ float sPart[540];                   // 12 tiles x 3 kq x 15
    __shared__ __align__(16) float sQ[9][PSTRQ];   // staged Q

    const int b  = blockIdx.z, cy = blockIdx.y, cx = blockIdx.x;
    const int tid = threadIdx.x;

    // Thread's pixel quad
    const int ty  = tid >> 2;
    const int tx0 = (tid & 3) * 4;
    const float* xp = x + (size_t)b * C_ * HW_
                        + (size_t)(cy * CELL_ + ty) * W_ + (cx * CELL_ + tx0);
    const int p0 = tid * 4;

    // PREFETCH: channel group g=0 (independent of smem) before the barrier
    float4 xg0[4];
#pragma unroll
    for (int j = 0; j < 4; j++)
        xg0[j] = *(const float4*)(xp + (size_t)j * HW_);

    // Seed tile (pre-doubled) + neighbor indices, strided over 64 threads.
    // SRC>0: fused division numer/(denom+eps) replaces the k_update kernel.
    for (int t = tid; t < 180; t += 64) {
        const int o = t / 20, c = t - o * 20;
        int iy = cy + c_dy[o]; iy = iy < 0 ? 0 : (iy > SH_ - 1 ? SH_ - 1 : iy);
        int ix = cx + c_dx[o]; ix = ix < 0 ? 0 : (ix > SW_ - 1 ? SW_ - 1 : ix);
        const int sidx = iy * SW_ + ix;
        if (c == 0) sIdx[o] = sidx;
        float sv;
        if (SRC == 0) {
            sv = g_seeds[b][sidx][c];
        } else {
            sv = g_numerB[SRC - 1][b][sidx][c]
               / (g_denomB[SRC - 1][b][sidx] + EPSV);
        }
        sS[o][c] = 2.f * sv;
    }
    __syncthreads();

    if (tid < 9) {
        float a = 0.f;
#pragma unroll
        for (int c = 0; c < C_; c++) a += sS[tid][c] * sS[tid][c];
        sD0[tid] = 0.25f * a;   // sS holds 2s
    }

    // Logits streamed by channel groups of 4 (g=0 peeled, uses prefetch)
    float4 L[9];
#pragma unroll
    for (int o = 0; o < 9; o++) L[o] = make_float4(0.f, 0.f, 0.f, 0.f);

#pragma unroll
    for (int o = 0; o < 9; o++) {
        const float4 s4 = *(const float4*)&sS[o][0];
        L[o].x = fmaf(s4.x, xg0[0].x, L[o].x);
        L[o].y = fmaf(s4.x, xg0[0].y, L[o].y);
        L[o].z = fmaf(s4.x, xg0[0].z, L[o].z);
        L[o].w = fmaf(s4.x, xg0[0].w, L[o].w);
        L[o].x = fmaf(s4.y, xg0[1].x, L[o].x);
        L[o].y = fmaf(s4.y, xg0[1].y, L[o].y);
        L[o].z = fmaf(s4.y, xg0[1].z, L[o].z);
        L[o].w = fmaf(s4.y, xg0[1].w, L[o].w);
        L[o].x = fmaf(s4.z, xg0[2].x, L[o].x);
        L[o].y = fmaf(s4.z, xg0[2].y, L[o].y);
        L[o].z = fmaf(s4.z, xg0[2].z, L[o].z);
        L[o].w = fmaf(s4.z, xg0[2].w, L[o].w);
        L[o].x = fmaf(s4.w, xg0[3].x, L[o].x);
        L[o].y = fmaf(s4.w, xg0[3].y, L[o].y);
        L[o].z = fmaf(s4.w, xg0[3].z, L[o].z);
        L[o].w = fmaf(s4.w, xg0[3].w, L[o].w);
    }

#pragma unroll
    for (int g = 1; g < 5; g++) {
        float4 xg[4];
#pragma unroll
        for (int j = 0; j < 4; j++)
            xg[j] = *(const float4*)(xp + (size_t)(4 * g + j) * HW_);
#pragma unroll
        for (int o = 0; o < 9; o++) {
            const float4 s4 = *(const float4*)&sS[o][4 * g];
            L[o].x = fmaf(s4.x, xg[0].x, L[o].x);
            L[o].y = fmaf(s4.x, xg[0].y, L[o].y);
            L[o].z = fmaf(s4.x, xg[0].z, L[o].z);
            L[o].w = fmaf(s4.x, xg[0].w, L[o].w);
            L[o].x = fmaf(s4.y, xg[1].x, L[o].x);
            L[o].y = fmaf(s4.y, xg[1].y, L[o].y);
            L[o].z = fmaf(s4.y, xg[1].z, L[o].z);
            L[o].w = fmaf(s4.y, xg[1].w, L[o].w);
            L[o].x = fmaf(s4.z, xg[2].x, L[o].x);
            L[o].y = fmaf(s4.z, xg[2].y, L[o].y);
            L[o].z = fmaf(s4.z, xg[2].z, L[o].z);
            L[o].w = fmaf(s4.z, xg[2].w, L[o].w);
            L[o].x = fmaf(s4.w, xg[3].x, L[o].x);
            L[o].y = fmaf(s4.w, xg[3].y, L[o].y);
            L[o].z = fmaf(s4.w, xg[3].z, L[o].z);
            L[o].w = fmaf(s4.w, xg[3].w, L[o].w);
        }
    }
    __syncthreads();   // sD0 ready

    // Subtract |s|^2, softmax over o (componentwise over the 4 pixels)
#pragma unroll
    for (int o = 0; o < 9; o++) {
        const float d0 = sD0[o];
        L[o].x -= d0; L[o].y -= d0; L[o].z -= d0; L[o].w -= d0;
    }
    float4 m = L[0];
#pragma unroll
    for (int o = 1; o < 9; o++) {
        m.x = fmaxf(m.x, L[o].x); m.y = fmaxf(m.y, L[o].y);
        m.z = fmaxf(m.z, L[o].z); m.w = fmaxf(m.w, L[o].w);
    }
    float4 sum = make_float4(0.f, 0.f, 0.f, 0.f);
#pragma unroll
    for (int o = 0; o < 9; o++) {
        L[o].x = __expf(L[o].x - m.x); sum.x += L[o].x;
        L[o].y = __expf(L[o].y - m.y); sum.y += L[o].y;
        L[o].z = __expf(L[o].z - m.z); sum.z += L[o].z;
        L[o].w = __expf(L[o].w - m.w); sum.w += L[o].w;
    }
    const float4 inv = make_float4(1.f / sum.x, 1.f / sum.y,
                                   1.f / sum.z, 1.f / sum.w);
#pragma unroll
    for (int o = 0; o < 9; o++) {
        L[o].x *= inv.x; L[o].y *= inv.y; L[o].z *= inv.z; L[o].w *= inv.w;
    }

    if constexpr (FINAL) {
        const int yy = cy * CELL_ + ty, xx = cx * CELL_ + tx0;
        float* op = out + (size_t)b * 9 * HW_ + (size_t)yy * W_ + xx;
#pragma unroll
        for (int o = 0; o < 9; o++) *(float4*)(op + (size_t)o * HW_) = L[o];
        return;
    } else {

    // Stage Q + per-thread denom quad sums
    float qs[9];
#pragma unroll
    for (int o = 0; o < 9; o++) {
        *(float4*)&sQ[o][p0] = L[o];
        qs[o] = (L[o].x + L[o].y) + (L[o].z + L[o].w);
    }
    // warp butterfly: all lanes end with warp total
#pragma unroll
    for (int o = 0; o < 9; o++) {
#pragma unroll
        for (int d = 16; d >= 1; d >>= 1)
            qs[o] += __shfl_xor_sync(0xffffffffu, qs[o], d);
    }
    if (tid == 32) {
#pragma unroll
        for (int o = 0; o < 9; o++) sDen[o] = qs[o];
    }

    // GEMM setup + PREFETCH of i=0 X chunks before the Q-staging barrier
    const int t2 = tid >> 2, kq = tid & 3;
    const int og = t2 % 3, cgr = t2 / 3;
    const float4* px[5];
    float4 xpre[5];
    if (tid < 48) {
        const float4* xb = (const float4*)(x + (size_t)b * C_ * HW_
                                             + (size_t)(cy * CELL_) * W_
                                             + cx * CELL_);
#pragma unroll
        for (int jc = 0; jc < 5; jc++) {
            px[jc] = xb + (size_t)(5 * cgr + jc) * (HW_ / 4) + kq;
            xpre[jc] = px[jc][0];
        }
    }
    __syncthreads();   // Q staged + sDen ready

    if (tid == 0) {
#pragma unroll
        for (int o = 0; o < 9; o++)
            atomicAdd(&g_denomB[SRC][b][sIdx[o]], qs[o] + sDen[o]);
    }

    // Reduction GEMM: 48 threads = 12 tiles (3o x 5c) x 4 K-slices (kq).
    float acc[3][5];
#pragma unroll
    for (int jo = 0; jo < 3; jo++)
#pragma unroll
        for (int jc = 0; jc < 5; jc++) acc[jo][jc] = 0.f;

    if (tid < 48) {
        // i = 0 peeled (uses prefetched X)
        {
            float4 qv[3];
#pragma unroll
            for (int jo = 0; jo < 3; jo++)
                qv[jo] = ((const float4*)&sQ[3 * og + jo][0])[kq];
#pragma unroll
            for (int jc = 0; jc < 5; jc++) {
                const float4 xc = xpre[jc];
#pragma unroll
                for (int jo = 0; jo < 3; jo++) {
                    acc[jo][jc] = fmaf(xc.x, qv[jo].x, acc[jo][jc]);
                    acc[jo][jc] = fmaf(xc.y, qv[jo].y, acc[jo][jc]);
                    acc[jo][jc] = fmaf(xc.z, qv[jo].z, acc[jo][jc]);
                    acc[jo][jc] = fmaf(xc.w, qv[jo].w, acc[jo][jc]);
                }
            }
        }
#pragma unroll 3
        for (int i = 1; i < 16; i++) {
            const int ck = 4 * i + kq;
            float4 qv[3];
#pragma unroll
            for (int jo = 0; jo < 3; jo++)
                qv[jo] = ((const float4*)&sQ[3 * og + jo][0])[ck];
#pragma unroll
            for (int jc = 0; jc < 5; jc++) {
                const float4 xc = px[jc][i * (W_ / 4)];
#pragma unroll
                for (int jo = 0; jo < 3; jo++) {
                    acc[jo][jc] = fmaf(xc.x, qv[jo].x, acc[jo][jc]);
                    acc[jo][jc] = fmaf(xc.y, qv[jo].y, acc[jo][jc]);
                    acc[jo][jc] = fmaf(xc.z, qv[jo].z, acc[jo][jc]);
                    acc[jo][jc] = fmaf(xc.w, qv[jo].w, acc[jo][jc]);
                }
            }
        }
    }

    if (tid < 48 && kq > 0) {
        float* dst = &sPart[(t2 * 3 + (kq - 1)) * 15];
#pragma unroll
        for (int jo = 0; jo < 3; jo++)
#pragma unroll
            for (int jc = 0; jc < 5; jc++) dst[jo * 5 + jc] = acc[jo][jc];
    }
    __syncthreads();   // unconditional

    if (tid < 48 && kq == 0) {
#pragma unroll
        for (int p = 0; p < 3; p++) {
            const float* src = &sPart[(t2 * 3 + p) * 15];
#pragma unroll
            for (int jo = 0; jo < 3; jo++)
#pragma unroll
                for (int jc = 0; jc < 5; jc++) acc[jo][jc] += src[jo * 5 + jc];
        }
#pragma unroll
        for (int jo = 0; jo < 3; jo++) {
            const int sidx = sIdx[3 * og + jo];
#pragma unroll
            for (int jc = 0; jc < 5; jc++)
                atomicAdd(&g_numerB[SRC][b][sidx][5 * cgr + jc], acc[jo][jc]);
        }
    }
    }  // !FINAL
}

// ---------------------------------------------------------------------------
extern "C" void kernel_launch(void* const* d_in, const int* in_sizes, int n_in,
                              void* d_out, int out_size)
{
    const float* x = (const float*)d_in[0];
    float* out = (float*)d_out;

    dim3 grid(SW_, SH_, B_);

    k_init<<<grid, 256>>>(x);
    k_main<0, false><<<grid, 64>>>(x, nullptr);   // seeds=means  -> buf0
    k_main<1, false><<<grid, 64>>>(x, nullptr);   // seeds=buf0   -> buf1
    k_main<2, false><<<grid, 64>>>(x, nullptr);   // seeds=buf1   -> buf2
    k_main<3, true ><<<grid, 64>>>(x, out);       // seeds=buf2   -> output
}

// round 13
// speedup vs baseline: 1.9867x; 1.0022x over previous
#include <cuda_runtime.h>

#define B_    8
#define C_    20
#define H_    512
#define W_    512
#define SH_   32
#define SW_   32
#define S_    1024
#define CELL_ 16
#define HW_   (H_*W_)
#define PSTR  260
#define PSTRQ 264            // Q staging stride (floats): 66 16B-chunks
#define EPSV  1e-8f

typedef unsigned long long u64;

// Packed fp32x2 helpers (SASS FFMA2 — PTX-only per sm_103a quickref)
__device__ __forceinline__ u64 pkdup(float s) {
    u64 r; asm("mov.b64 %0,{%1,%1};" : "=l"(r) : "f"(s)); return r;
}
__device__ __forceinline__ void upk2(u64 v, float& lo, float& hi) {
    asm("mov.b64 {%0,%1},%2;" : "=f"(lo), "=f"(hi) : "l"(v));
}
__device__ __forceinline__ u64 fma2(u64 a, u64 b, u64 c) {
    u64 d; asm("fma.rn.f32x2 %0,%1,%2,%3;" : "=l"(d) : "l"(a), "l"(b), "l"(c));
    return d;
}

__device__ float g_seeds[B_][S_][C_];          // iteration-0 seeds (means)
__device__ float g_numerB[3][B_][S_][C_];      // per-iteration accumulators
__device__ float g_denomB[3][B_][S_];

__constant__ int c_dy[9] = {-1,-1,-1, 0,0,0, 1,1,1};
__constant__ int c_dx[9] = {-1, 0, 1,-1,0,1,-1,0,1};

// ---------------------------------------------------------------------------
// K0: seed init = 16x16 mean pool per (b, cell, c); zero ALL 3 accumulator
// buffers (seed division is fused into k_main's seed loader).
// ---------------------------------------------------------------------------
__global__ void __launch_bounds__(256) k_init(const float* __restrict__ x)
{
    __shared__ __align__(16) float sX[C_][PSTR];
    const int b  = blockIdx.z, cy = blockIdx.y, cx = blockIdx.x;
    const int tid = threadIdx.x;
    const int ty = tid >> 4, tx = tid & 15;
    const int sidx = cy * SW_ + cx;

    if (tid < 63) {
        const int buf = tid / 21, c = tid % 21;
        if (c < 20) g_numerB[buf][b][sidx][c] = 0.f;
        else        g_denomB[buf][b][sidx]    = 0.f;
    }

    const float* xp = x + (size_t)b * C_ * HW_
                        + (size_t)(cy * CELL_ + ty) * W_ + (cx * CELL_ + tx);
#pragma unroll
    for (int c = 0; c < C_; c++) sX[c][tid] = xp[(size_t)c * HW_];
    __syncthreads();

    if (tid < C_) {
        const float4* r = (const float4*)sX[tid];
        float a0 = 0.f, a1 = 0.f, a2 = 0.f, a3 = 0.f;
#pragma unroll
        for (int p = 0; p < 64; p++) {
            float4 v = r[p];
            a0 += v.x; a1 += v.y; a2 += v.z; a3 += v.w;
        }
        g_seeds[b][sidx][tid] = ((a0 + a1) + (a2 + a3)) * (1.f / 256.f);
    }
}

// ---------------------------------------------------------------------------
// Main kernel: one CTA = one (b, cell). 64 threads, thread = 4 adjacent px.
// logit[o] = 2*x.s_o - |s_o|^2  (|x|^2 cancels in softmax over o)
// All heavy FMA work uses packed fp32x2 (FFMA2): x/Q pairs come packed for
// free from float4 loads (ulonglong2 reinterpret); seeds dup-packed via mov.
// SRC = 0: seeds from g_seeds; SRC>0: seeds = numerB[SRC-1]/denomB[SRC-1].
// ---------------------------------------------------------------------------
template<int SRC, bool FINAL>
__global__ void __launch_bounds__(64, 10) k_main(const float* __restrict__ x,
                                                 float* __restrict__ out)
{
    __shared__ __align__(16) float sS[9][20];      // 2*seed
    __shared__ float sD0[9];                       // |seed|^2
    __shared__ int   sIdx[9];                      // clipped global seed index
    __shared__ float sDen[9];                      // warp-1 denom partials
    __shared__ float sPart[540];                   // 12 tiles x 3 kq x 15
    __shared__ __align__(16) float sQ[9][PSTRQ];   // staged Q

    const int b  = blockIdx.z, cy = blockIdx.y, cx = blockIdx.x;
    const int tid = threadIdx.x;

    // Thread's pixel quad
    const int ty  = tid >> 2;
    const int tx0 = (tid & 3) * 4;
    const float* xp = x + (size_t)b * C_ * HW_
                        + (size_t)(cy * CELL_ + ty) * W_ + (cx * CELL_ + tx0);
    const ulonglong2* xq = (const ulonglong2*)xp;     // 16B packed view
    const int p0 = tid * 4;

    // PREFETCH: channel group g=0 before the seed barrier
    ulonglong2 xg0[4];
#pragma unroll
    for (int j = 0; j < 4; j++) xg0[j] = xq[(size_t)j * (HW_ / 4)];

    // Seed tile (pre-doubled) + neighbor indices, strided over 64 threads.
    for (int t = tid; t < 180; t += 64) {
        const int o = t / 20, c = t - o * 20;
        int iy = cy + c_dy[o]; iy = iy < 0 ? 0 : (iy > SH_ - 1 ? SH_ - 1 : iy);
        int ix = cx + c_dx[o]; ix = ix < 0 ? 0 : (ix > SW_ - 1 ? SW_ - 1 : ix);
        const int sidx = iy * SW_ + ix;
        if (c == 0) sIdx[o] = sidx;
        float sv;
        if (SRC == 0) {
            sv = g_seeds[b][sidx][c];
        } else {
            sv = g_numerB[SRC - 1][b][sidx][c]
               / (g_denomB[SRC - 1][b][sidx] + EPSV);
        }
        sS[o][c] = 2.f * sv;
    }
    __syncthreads();

    if (tid < 9) {
        float a = 0.f;
#pragma unroll
        for (int c = 0; c < C_; c++) a += sS[tid][c] * sS[tid][c];
        sD0[tid] = 0.25f * a;   // sS holds 2s
    }

    // Logits, packed: L01 = pixels 0,1 ; L23 = pixels 2,3
    u64 L01[9], L23[9];
#pragma unroll
    for (int o = 0; o < 9; o++) { L01[o] = 0ull; L23[o] = 0ull; }

#pragma unroll
    for (int g = 0; g < 5; g++) {
        ulonglong2 xg[4];
        if (g == 0) {
#pragma unroll
            for (int j = 0; j < 4; j++) xg[j] = xg0[j];
        } else {
#pragma unroll
            for (int j = 0; j < 4; j++)
                xg[j] = xq[(size_t)(4 * g + j) * (HW_ / 4)];
        }
#pragma unroll
        for (int o = 0; o < 9; o++) {
            const float4 s4 = *(const float4*)&sS[o][4 * g];
            const u64 b0 = pkdup(s4.x), b1 = pkdup(s4.y);
            const u64 b2 = pkdup(s4.z), b3 = pkdup(s4.w);
            L01[o] = fma2(xg[0].x, b0, L01[o]);
            L23[o] = fma2(xg[0].y, b0, L23[o]);
            L01[o] = fma2(xg[1].x, b1, L01[o]);
            L23[o] = fma2(xg[1].y, b1, L23[o]);
            L01[o] = fma2(xg[2].x, b2, L01[o]);
            L23[o] = fma2(xg[2].y, b2, L23[o]);
            L01[o] = fma2(xg[3].x, b3, L01[o]);
            L23[o] = fma2(xg[3].y, b3, L23[o]);
        }
    }
    __syncthreads();   // sD0 ready

    // Unpack logits, subtract |s|^2, softmax over o
    float4 L[9];
#pragma unroll
    for (int o = 0; o < 9; o++) {
        upk2(L01[o], L[o].x, L[o].y);
        upk2(L23[o], L[o].z, L[o].w);
        const float d0 = sD0[o];
        L[o].x -= d0; L[o].y -= d0; L[o].z -= d0; L[o].w -= d0;
    }
    float4 m = L[0];
#pragma unroll
    for (int o = 1; o < 9; o++) {
        m.x = fmaxf(m.x, L[o].x); m.y = fmaxf(m.y, L[o].y);
        m.z = fmaxf(m.z, L[o].z); m.w = fmaxf(m.w, L[o].w);
    }
    float4 sum = make_float4(0.f, 0.f, 0.f, 0.f);
#pragma unroll
    for (int o = 0; o < 9; o++) {
        L[o].x = __expf(L[o].x - m.x); sum.x += L[o].x;
        L[o].y = __expf(L[o].y - m.y); sum.y += L[o].y;
        L[o].z = __expf(L[o].z - m.z); sum.z += L[o].z;
        L[o].w = __expf(L[o].w - m.w); sum.w += L[o].w;
    }
    const float4 inv = make_float4(1.f / sum.x, 1.f / sum.y,
                                   1.f / sum.z, 1.f / sum.w);
#pragma unroll
    for (int o = 0; o < 9; o++) {
        L[o].x *= inv.x; L[o].y *= inv.y; L[o].z *= inv.z; L[o].w *= inv.w;
    }

    if constexpr (FINAL) {
        const int yy = cy * CELL_ + ty, xx = cx * CELL_ + tx0;
        float* op = out + (size_t)b * 9 * HW_ + (size_t)yy * W_ + xx;
#pragma unroll
        for (int o = 0; o < 9; o++) *(float4*)(op + (size_t)o * HW_) = L[o];
        return;
    } else {

    // Stage Q + per-thread denom quad sums
    float qs[9];
#pragma unroll
    for (int o = 0; o < 9; o++) {
        *(float4*)&sQ[o][p0] = L[o];
        qs[o] = (L[o].x + L[o].y) + (L[o].z + L[o].w);
    }
#pragma unroll
    for (int o = 0; o < 9; o++) {
#pragma unroll
        for (int d = 16; d >= 1; d >>= 1)
            qs[o] += __shfl_xor_sync(0xffffffffu, qs[o], d);
    }
    if (tid == 32) {
#pragma unroll
        for (int o = 0; o < 9; o++) sDen[o] = qs[o];
    }

    // GEMM setup + prefetch of i=0 X chunks before the Q-staging barrier
    const int t2 = tid >> 2, kq = tid & 3;
    const int og = t2 % 3, cgr = t2 / 3;
    const ulonglong2* px[5];
    ulonglong2 xpre[5];
    if (tid < 48) {
        const ulonglong2* xb = (const ulonglong2*)(x + (size_t)b * C_ * HW_
                                                     + (size_t)(cy * CELL_) * W_
                                                     + cx * CELL_);
#pragma unroll
        for (int jc = 0; jc < 5; jc++) {
            px[jc] = xb + (size_t)(5 * cgr + jc) * (HW_ / 4) + kq;
            xpre[jc] = px[jc][0];
        }
    }
    __syncthreads();   // Q staged + sDen ready

    if (tid == 0) {
#pragma unroll
        for (int o = 0; o < 9; o++)
            atomicAdd(&g_denomB[SRC][b][sIdx[o]], qs[o] + sDen[o]);
    }

    // Reduction GEMM, packed: 48 threads = 12 tiles (3o x 5c) x 4 K-slices.
    u64 acc2[3][5];
#pragma unroll
    for (int jo = 0; jo < 3; jo++)
#pragma unroll
        for (int jc = 0; jc < 5; jc++) acc2[jo][jc] = 0ull;

    if (tid < 48) {
        const ulonglong2* sQu[3];
#pragma unroll
        for (int jo = 0; jo < 3; jo++)
            sQu[jo] = (const ulonglong2*)&sQ[3 * og + jo][0];
        // i = 0 peeled (prefetched X)
        {
            ulonglong2 qv[3];
#pragma unroll
            for (int jo = 0; jo < 3; jo++) qv[jo] = sQu[jo][kq];
#pragma unroll
            for (int jc = 0; jc < 5; jc++) {
                const ulonglong2 xc = xpre[jc];
#pragma unroll
                for (int jo = 0; jo < 3; jo++) {
                    acc2[jo][jc] = fma2(xc.x, qv[jo].x, acc2[jo][jc]);
                    acc2[jo][jc] = fma2(xc.y, qv[jo].y, acc2[jo][jc]);
                }
            }
        }
#pragma unroll 3
        for (int i = 1; i < 16; i++) {
            const int ck = 4 * i + kq;
            ulonglong2 qv[3];
#pragma unroll
            for (int jo = 0; jo < 3; jo++) qv[jo] = sQu[jo][ck];
#pragma unroll
            for (int jc = 0; jc < 5; jc++) {
                const ulonglong2 xc = px[jc][(size_t)i * (W_ / 4)];
#pragma unroll
                for (int jo = 0; jo < 3; jo++) {
                    acc2[jo][jc] = fma2(xc.x, qv[jo].x, acc2[jo][jc]);
                    acc2[jo][jc] = fma2(xc.y, qv[jo].y, acc2[jo][jc]);
                }
            }
        }
    }

    // Collapse packed lanes to scalar partials
    float acc[3][5];
#pragma unroll
    for (int jo = 0; jo < 3; jo++)
#pragma unroll
        for (int jc = 0; jc < 5; jc++) {
            float lo, hi; upk2(acc2[jo][jc], lo, hi);
            acc[jo][jc] = lo + hi;
        }

    if (tid < 48 && kq > 0) {
        float* dst = &sPart[(t2 * 3 + (kq - 1)) * 15];
#pragma unroll
        for (int jo = 0; jo < 3; jo++)
#pragma unroll
            for (int jc = 0; jc < 5; jc++) dst[jo * 5 + jc] = acc[jo][jc];
    }
    __syncthreads();   // unconditional

    if (tid < 48 && kq == 0) {
#pragma unroll
        for (int p = 0; p < 3; p++) {
            const float* src = &sPart[(t2 * 3 + p) * 15];
#pragma unroll
            for (int jo = 0; jo < 3; jo++)
#pragma unroll
                for (int jc = 0; jc < 5; jc++) acc[jo][jc] += src[jo * 5 + jc];
        }
#pragma unroll
        for (int jo = 0; jo < 3; jo++) {
            const int sidx = sIdx[3 * og + jo];
#pragma unroll
            for (int jc = 0; jc < 5; jc++)
                atomicAdd(&g_numerB[SRC][b][sidx][5 * cgr + jc], acc[jo][jc]);
        }
    }
    }  // !FINAL
}

// ---------------------------------------------------------------------------
extern "C" void kernel_launch(void* const* d_in, const int* in_sizes, int n_in,
                              void* d_out, int out_size)
{
    const float* x = (const float*)d_in[0];
    float* out = (float*)d_out;

    dim3 grid(SW_, SH_, B_);

    k_init<<<grid, 256>>>(x);
    k_main<0, false><<<grid, 64>>>(x, nullptr);   // seeds=means  -> buf0
    k_main<1, false><<<grid, 64>>>(x, nullptr);   // seeds=buf0   -> buf1
    k_main<2, false><<<grid, 64>>>(x, nullptr);   // seeds=buf1   -> buf2
    k_main<3, true ><<<grid, 64>>>(x, out);       // seeds=buf2   -> output
}